// round 3
// baseline (speedup 1.0000x reference)
#include <cuda_runtime.h>
#include <cstdint>

#define Dd 1024
#define Bb 16
#define Tt 1024
#define NBLK 128
#define MAXR 0.999f
#define EPSF 1e-8f

// ---------------- device scratch (no allocation allowed) ----------------
__device__ float g_WhEff[Dd * Dd];                 // 4 MB
__device__ float g_pre[(size_t)Tt * Bb * Dd];      // 64 MB: x @ Wx^T + bias
__device__ float g_sigma;
__device__ unsigned g_arrive;

// ---------------- f32x2 helpers (sm_103a packed fp32) ----------------
__device__ __forceinline__ unsigned long long pk2(float lo, float hi) {
    unsigned long long r;
    asm("mov.b64 %0, {%1, %2};" : "=l"(r) : "f"(lo), "f"(hi));
    return r;
}
__device__ __forceinline__ float2 up2(unsigned long long v) {
    float2 r;
    asm("mov.b64 {%0, %1}, %2;" : "=f"(r.x), "=f"(r.y) : "l"(v));
    return r;
}
__device__ __forceinline__ void fma2(unsigned long long& d, unsigned long long a,
                                     unsigned long long b) {
    asm("fma.rn.f32x2 %0, %1, %2, %0;" : "+l"(d) : "l"(a), "l"(b));
}
__device__ __forceinline__ unsigned long long add2(unsigned long long a,
                                                   unsigned long long b) {
    unsigned long long r;
    asm("add.rn.f32x2 %0, %1, %2;" : "=l"(r) : "l"(a), "l"(b));
    return r;
}

// ---------------- per-launch init (device globals persist across replays) ---
__global__ void init_kernel() { g_arrive = 0u; }

// ---------------- block-wide sum (1024 threads) ----------------
__device__ __forceinline__ float blk_sum(float v, float* red) {
    int lane = threadIdx.x & 31, warp = threadIdx.x >> 5;
#pragma unroll
    for (int off = 16; off > 0; off >>= 1) v += __shfl_xor_sync(0xffffffffu, v, off);
    if (lane == 0) red[warp] = v;
    __syncthreads();
    if (warp == 0) {
        float x = red[lane];
#pragma unroll
        for (int off = 16; off > 0; off >>= 1) x += __shfl_xor_sync(0xffffffffu, x, off);
        if (lane == 0) red[0] = x;
    }
    __syncthreads();
    float r = red[0];
    __syncthreads();
    return r;
}

// ---------------- 3-step power iteration -> g_sigma ----------------
__global__ void __launch_bounds__(1024) power_iter_kernel(
        const float* __restrict__ Wh, const float* __restrict__ u0) {
    __shared__ float su[Dd];
    __shared__ float sv[Dd];
    __shared__ float red[32];
    const int tid = threadIdx.x;
    su[tid] = u0[tid];
    __syncthreads();

    float normsq_last = 0.f, nu_last = 0.f;
    for (int it = 0; it < 3; it++) {
        float acc = 0.f;
        for (int i = 0; i < Dd; i++) acc += Wh[(size_t)i * Dd + tid] * su[i];
        float nv = sqrtf(blk_sum(acc * acc, red)) + EPSF;
        sv[tid] = acc / nv;
        __syncthreads();
        float acc2 = 0.f;
        const float* row = Wh + (size_t)tid * Dd;
        for (int j = 0; j < Dd; j++) acc2 += row[j] * sv[j];
        float nsq = blk_sum(acc2 * acc2, red);
        float nu = sqrtf(nsq);
        su[tid] = acc2 / (nu + EPSF);
        __syncthreads();
        if (it == 2) { normsq_last = nsq; nu_last = nu; }
    }
    if (tid == 0) g_sigma = fabsf(normsq_last / (nu_last + EPSF));
}

// ---------------- W_h_eff = W_h * radii[i] / (sigma + eps) ----------------
__global__ void __launch_bounds__(256) scale_wh_kernel(
        const float* __restrict__ Wh, const float* __restrict__ log_radii) {
    const int i = blockIdx.x;
    const float r = (1.f / (1.f + expf(-log_radii[i]))) * MAXR;
    const float scale = r / (g_sigma + EPSF);
    const float4* src = (const float4*)(Wh + (size_t)i * Dd);
    float4* dst = (float4*)(g_WhEff + (size_t)i * Dd);
    int j = threadIdx.x;
    float4 v = src[j];
    v.x *= scale; v.y *= scale; v.z *= scale; v.w *= scale;
    dst[j] = v;
}

// ---------------- SGEMM with packed f32x2 FMA ----------------
// g_pre[m][n] = sum_k x[m][k] * Wx[n][k] + b[n]; M=16384, N=1024, K=1024.
__global__ void __launch_bounds__(256) gemm_kernel(
        const float* __restrict__ A, const float* __restrict__ W,
        const float* __restrict__ bias) {
    __shared__ float As[16][132];
    __shared__ float Bs[16][132];
    const int tid = threadIdx.x;
    const int tx = tid & 15, ty = tid >> 4;
    const int m0 = blockIdx.y * 128, n0 = blockIdx.x * 128;
    const int lrow = tid >> 2, lcol = (tid & 3) << 2;

    const float* Aptr = A + (size_t)(m0 + lrow) * Dd + lcol;
    const float* Wptr = W + (size_t)(n0 + lrow) * Dd + lcol;

    float4 a0 = *(const float4*)(Aptr);
    float4 a1 = *(const float4*)(Aptr + (size_t)64 * Dd);
    float4 b0 = *(const float4*)(Wptr);
    float4 b1 = *(const float4*)(Wptr + (size_t)64 * Dd);

    unsigned long long acc2[8][4];
#pragma unroll
    for (int i = 0; i < 8; i++)
#pragma unroll
        for (int j = 0; j < 4; j++) acc2[i][j] = 0ULL;

    for (int k0 = 0; k0 < Dd; k0 += 16) {
        __syncthreads();
        As[lcol + 0][lrow] = a0.x; As[lcol + 1][lrow] = a0.y;
        As[lcol + 2][lrow] = a0.z; As[lcol + 3][lrow] = a0.w;
        As[lcol + 0][lrow + 64] = a1.x; As[lcol + 1][lrow + 64] = a1.y;
        As[lcol + 2][lrow + 64] = a1.z; As[lcol + 3][lrow + 64] = a1.w;
        Bs[lcol + 0][lrow] = b0.x; Bs[lcol + 1][lrow] = b0.y;
        Bs[lcol + 2][lrow] = b0.z; Bs[lcol + 3][lrow] = b0.w;
        Bs[lcol + 0][lrow + 64] = b1.x; Bs[lcol + 1][lrow + 64] = b1.y;
        Bs[lcol + 2][lrow + 64] = b1.z; Bs[lcol + 3][lrow + 64] = b1.w;
        __syncthreads();

        if (k0 + 16 < Dd) {
            a0 = *(const float4*)(Aptr + k0 + 16);
            a1 = *(const float4*)(Aptr + (size_t)64 * Dd + k0 + 16);
            b0 = *(const float4*)(Wptr + k0 + 16);
            b1 = *(const float4*)(Wptr + (size_t)64 * Dd + k0 + 16);
        }

#pragma unroll
        for (int k = 0; k < 16; k++) {
            float ar[8];
            *(float4*)(ar) = *(const float4*)&As[k][ty * 8];
            *(float4*)(ar + 4) = *(const float4*)&As[k][ty * 8 + 4];
            unsigned long long brp[4];
            const unsigned long long* b64 = (const unsigned long long*)&Bs[k][tx * 8];
            brp[0] = b64[0]; brp[1] = b64[1]; brp[2] = b64[2]; brp[3] = b64[3];
#pragma unroll
            for (int i = 0; i < 8; i++) {
                unsigned long long ad = pk2(ar[i], ar[i]);
#pragma unroll
                for (int j = 0; j < 4; j++) fma2(acc2[i][j], ad, brp[j]);
            }
        }
    }

    float bj[8];
#pragma unroll
    for (int j = 0; j < 8; j++) bj[j] = bias[n0 + tx * 8 + j];
#pragma unroll
    for (int i = 0; i < 8; i++) {
        float* Crow = g_pre + (size_t)(m0 + ty * 8 + i) * Dd + n0 + tx * 8;
        float c[8];
#pragma unroll
        for (int j = 0; j < 4; j++) {
            float2 f = up2(acc2[i][j]);
            c[2 * j] = f.x + bj[2 * j];
            c[2 * j + 1] = f.y + bj[2 * j + 1];
        }
        *(float4*)(Crow) = make_float4(c[0], c[1], c[2], c[3]);
        *(float4*)(Crow + 4) = make_float4(c[4], c[5], c[6], c[7]);
    }
}

// ---------------- persistent recurrence ----------------
// 128 blocks x 256 threads; block owns 8 output dims, all 16 batches.
// W slice (32KB) persistent in SMEM. h_prev streamed straight from L2 via
// LDG.128.cg (each h element consumed exactly once per block -> no staging).
// Warp tile: 8 dims x 4 batches, 2-warp k-split, packed f32x2 over k-pairs.
// Barrier: fire-and-forget RED arrival + direct poll on the counter.
__global__ void __launch_bounds__(256, 1) recurrent_kernel(
        const float* __restrict__ z, const float* __restrict__ h0,
        float* __restrict__ outs, float* __restrict__ hall) {
    __shared__ float sW[8 * Dd];      // 32 KB, persistent
    __shared__ float red[128];

    const int tid = threadIdx.x, bid = blockIdx.x;
    const int dbase = bid * 8;

    // preload my W_h_eff rows (persist across all steps)
    {
        const float4* wsrc = (const float4*)(g_WhEff + (size_t)dbase * Dd);
        for (int i = tid; i < 8 * Dd / 4; i += 256) ((float4*)sW)[i] = wsrc[i];
    }
    // write h_all[0] stripe (pure output; consumers read h0 input directly)
    if (tid < 128) {
        int b = tid >> 3, d = dbase + (tid & 7);
        hall[b * Dd + d] = h0[b * Dd + d];
    }
    __syncthreads();

    const int warp = tid >> 5, lane = tid & 31;
    const int tb = warp >> 1;   // batch group (4 batches)
    const int kw = warp & 1;    // k-split half
    const ulonglong2* w128 = (const ulonglong2*)sW;
    // float4-granule index of this thread's k-chunk for iteration 'it':
    //   d * 256 + kw * 128 + it * 32 + lane
    const int kbase = kw * 128 + lane;

    // epilogue mapping (tid < 128): one (batch, dim) output per thread
    const int eb = (tid >> 5) * 4 + (tid & 3);
    const int ed = dbase + ((tid >> 2) & 7);

    for (int t = 0; t < Tt; t++) {
        const size_t off_e = (size_t)t * Bb * Dd + (size_t)eb * Dd + ed;
        float pre_v = 0.f, z_v = 0.f;
        if (tid < 128) {       // prefetch DRAM operands; overlaps the barrier
            pre_v = __ldcg(g_pre + off_e);
            z_v = __ldcg(z + off_e);
        }

        // wait for h_prev (skip at t=0: h0 is a kernel input, already visible)
        if (t > 0) {
            if (tid == 0) {
                const unsigned target = (unsigned)t * NBLK;
                while (*(volatile unsigned*)&g_arrive < target) { }
                __threadfence();
            }
            __syncthreads();
        }

        // stream h straight from L2: 16 x LDG.128.cg, all in flight up front
        const ulonglong2* hsrc = (const ulonglong2*)
            ((t == 0) ? h0 : (hall + (size_t)t * Bb * Dd));
        ulonglong2 hv[4][4];
#pragma unroll
        for (int b = 0; b < 4; b++) {
            const ulonglong2* hb = hsrc + (size_t)(tb * 4 + b) * (Dd / 4);
#pragma unroll
            for (int it = 0; it < 4; it++)
                hv[b][it] = __ldcg(hb + kbase + it * 32);
        }

        // inner product: 8 dims x 4 batches, f32x2 over k-pairs
        unsigned long long acc[32];
#pragma unroll
        for (int i = 0; i < 32; i++) acc[i] = 0ULL;
#pragma unroll
        for (int it = 0; it < 4; it++) {
            ulonglong2 wv[8];
#pragma unroll
            for (int d = 0; d < 8; d++) wv[d] = w128[d * 256 + kbase + it * 32];
#pragma unroll
            for (int d = 0; d < 8; d++)
#pragma unroll
                for (int b = 0; b < 4; b++) {
                    fma2(acc[d * 4 + b], wv[d].x, hv[b][it].x);
                    fma2(acc[d * 4 + b], wv[d].y, hv[b][it].y);
                }
        }

        // butterfly-fold: lane l ends owning output index l (d = l>>2, b = l&3)
#pragma unroll
        for (int off = 16; off > 0; off >>= 1) {
#pragma unroll
            for (int j = 0; j < off; j++) {
                unsigned long long send = (lane & off) ? acc[j] : acc[j + off];
                unsigned long long recv = __shfl_xor_sync(0xffffffffu, send, off);
                acc[j] = add2((lane & off) ? acc[j + off] : acc[j], recv);
            }
        }
        float2 f2 = up2(acc[0]);
        const float myv = f2.x + f2.y;

        // cross-k-warp combine through smem
        const int ridx = tb * 32 + lane;
        if (kw == 0) red[ridx] = myv;
        __syncthreads();
        if (kw == 1) red[ridx] += myv;
        __syncthreads();

        // epilogue: 128 threads, one output each
        float hn = 0.f;
        if (tid < 128) {
            hn = tanhf(red[tid] + pre_v);
            hall[off_e + Bb * Dd] = hn;   // h_all[t+1]
        }
        __threadfence();
        __syncthreads();
        if (tid == 0) atomicAdd(&g_arrive, 1u);   // no return use -> RED
        // silu gate off the critical path
        if (tid < 128) {
            float sg = z_v / (1.f + expf(-z_v));
            outs[off_e] = hn * sg;
        }
    }
}

// ---------------- launch ----------------
extern "C" void kernel_launch(void* const* d_in, const int* in_sizes, int n_in,
                              void* d_out, int out_size) {
    const float* x   = (const float*)d_in[0];  // [T,B,D]
    const float* z   = (const float*)d_in[1];  // [T,B,D]
    const float* h0  = (const float*)d_in[2];  // [B,D]
    const float* Wx  = (const float*)d_in[3];  // [D,D]
    const float* Wh  = (const float*)d_in[4];  // [D,D]
    const float* lr  = (const float*)d_in[5];  // [D]
    const float* bia = (const float*)d_in[6];  // [D]
    const float* u0  = (const float*)d_in[7];  // [D]

    float* outs = (float*)d_out;                         // [T,B,D]
    float* hall = (float*)d_out + (size_t)Tt * Bb * Dd;  // [T+1,B,D]

    init_kernel<<<1, 1>>>();
    power_iter_kernel<<<1, 1024>>>(Wh, u0);
    scale_wh_kernel<<<Dd, 256>>>(Wh, lr);
    {
        dim3 grid(Dd / 128, (Tt * Bb) / 128);  // (8, 128)
        gemm_kernel<<<grid, 256>>>(x, Wx, bia);
    }
    recurrent_kernel<<<NBLK, 256>>>(z, h0, outs, hall);
}

// round 4
// speedup vs baseline: 1.0634x; 1.0634x over previous
#include <cuda_runtime.h>
#include <cstdint>

#define Dd 1024
#define Bb 16
#define Tt 1024
#define NBLK 128
#define GRPS 4
#define CPG 32      // CTAs per sync group
#define DC 32       // dims per CTA
#define BC 4        // batches per CTA (= batches per group)
#define MAXR 0.999f
#define EPSF 1e-8f

// ---------------- device scratch (no allocation allowed) ----------------
__device__ float g_WhEff[Dd * Dd];                 // 4 MB
__device__ float g_pre[(size_t)Tt * Bb * Dd];      // 64 MB: x @ Wx^T + bias
__device__ float g_sigma;
__device__ __align__(128) unsigned g_arr[GRPS * 32];  // arrival counters, 128B apart
__device__ __align__(128) unsigned g_rel[GRPS * 32];  // release words, 128B apart

// ---------------- f32x2 helpers (sm_103a packed fp32) ----------------
__device__ __forceinline__ unsigned long long pk2(float lo, float hi) {
    unsigned long long r;
    asm("mov.b64 %0, {%1, %2};" : "=l"(r) : "f"(lo), "f"(hi));
    return r;
}
__device__ __forceinline__ float2 up2(unsigned long long v) {
    float2 r;
    asm("mov.b64 {%0, %1}, %2;" : "=f"(r.x), "=f"(r.y) : "l"(v));
    return r;
}
__device__ __forceinline__ void fma2(unsigned long long& d, unsigned long long a,
                                     unsigned long long b) {
    asm("fma.rn.f32x2 %0, %1, %2, %0;" : "+l"(d) : "l"(a), "l"(b));
}
__device__ __forceinline__ unsigned long long add2(unsigned long long a,
                                                   unsigned long long b) {
    unsigned long long r;
    asm("add.rn.f32x2 %0, %1, %2;" : "=l"(r) : "l"(a), "l"(b));
    return r;
}

// ---------------- per-launch init (device globals persist across replays) ---
__global__ void init_kernel() {
    if (threadIdx.x < GRPS * 32) {
        g_arr[threadIdx.x] = 0u;
        g_rel[threadIdx.x] = 0u;
    }
}

// dummy launch so the recurrent kernel sits at ncu's -s 5 capture slot
__global__ void dummy_kernel() {}

// ---------------- block-wide sum (1024 threads) ----------------
__device__ __forceinline__ float blk_sum(float v, float* red) {
    int lane = threadIdx.x & 31, warp = threadIdx.x >> 5;
#pragma unroll
    for (int off = 16; off > 0; off >>= 1) v += __shfl_xor_sync(0xffffffffu, v, off);
    if (lane == 0) red[warp] = v;
    __syncthreads();
    if (warp == 0) {
        float x = red[lane];
#pragma unroll
        for (int off = 16; off > 0; off >>= 1) x += __shfl_xor_sync(0xffffffffu, x, off);
        if (lane == 0) red[0] = x;
    }
    __syncthreads();
    float r = red[0];
    __syncthreads();
    return r;
}

// ---------------- 3-step power iteration -> g_sigma ----------------
__global__ void __launch_bounds__(1024) power_iter_kernel(
        const float* __restrict__ Wh, const float* __restrict__ u0) {
    __shared__ float su[Dd];
    __shared__ float sv[Dd];
    __shared__ float red[32];
    const int tid = threadIdx.x;
    su[tid] = u0[tid];
    __syncthreads();

    float normsq_last = 0.f, nu_last = 0.f;
    for (int it = 0; it < 3; it++) {
        float acc = 0.f;
        for (int i = 0; i < Dd; i++) acc += Wh[(size_t)i * Dd + tid] * su[i];
        float nv = sqrtf(blk_sum(acc * acc, red)) + EPSF;
        sv[tid] = acc / nv;
        __syncthreads();
        float acc2 = 0.f;
        const float* row = Wh + (size_t)tid * Dd;
        for (int j = 0; j < Dd; j++) acc2 += row[j] * sv[j];
        float nsq = blk_sum(acc2 * acc2, red);
        float nu = sqrtf(nsq);
        su[tid] = acc2 / (nu + EPSF);
        __syncthreads();
        if (it == 2) { normsq_last = nsq; nu_last = nu; }
    }
    if (tid == 0) g_sigma = fabsf(normsq_last / (nu_last + EPSF));
}

// ---------------- W_h_eff = W_h * radii[i] / (sigma + eps) ----------------
__global__ void __launch_bounds__(256) scale_wh_kernel(
        const float* __restrict__ Wh, const float* __restrict__ log_radii) {
    const int i = blockIdx.x;
    const float r = (1.f / (1.f + expf(-log_radii[i]))) * MAXR;
    const float scale = r / (g_sigma + EPSF);
    const float4* src = (const float4*)(Wh + (size_t)i * Dd);
    float4* dst = (float4*)(g_WhEff + (size_t)i * Dd);
    int j = threadIdx.x;
    float4 v = src[j];
    v.x *= scale; v.y *= scale; v.z *= scale; v.w *= scale;
    dst[j] = v;
}

// ---------------- SGEMM with packed f32x2 FMA ----------------
// g_pre[m][n] = sum_k x[m][k] * Wx[n][k] + b[n]; M=16384, N=1024, K=1024.
__global__ void __launch_bounds__(256) gemm_kernel(
        const float* __restrict__ A, const float* __restrict__ W,
        const float* __restrict__ bias) {
    __shared__ float As[16][132];
    __shared__ float Bs[16][132];
    const int tid = threadIdx.x;
    const int tx = tid & 15, ty = tid >> 4;
    const int m0 = blockIdx.y * 128, n0 = blockIdx.x * 128;
    const int lrow = tid >> 2, lcol = (tid & 3) << 2;

    const float* Aptr = A + (size_t)(m0 + lrow) * Dd + lcol;
    const float* Wptr = W + (size_t)(n0 + lrow) * Dd + lcol;

    float4 a0 = *(const float4*)(Aptr);
    float4 a1 = *(const float4*)(Aptr + (size_t)64 * Dd);
    float4 b0 = *(const float4*)(Wptr);
    float4 b1 = *(const float4*)(Wptr + (size_t)64 * Dd);

    unsigned long long acc2[8][4];
#pragma unroll
    for (int i = 0; i < 8; i++)
#pragma unroll
        for (int j = 0; j < 4; j++) acc2[i][j] = 0ULL;

    for (int k0 = 0; k0 < Dd; k0 += 16) {
        __syncthreads();
        As[lcol + 0][lrow] = a0.x; As[lcol + 1][lrow] = a0.y;
        As[lcol + 2][lrow] = a0.z; As[lcol + 3][lrow] = a0.w;
        As[lcol + 0][lrow + 64] = a1.x; As[lcol + 1][lrow + 64] = a1.y;
        As[lcol + 2][lrow + 64] = a1.z; As[lcol + 3][lrow + 64] = a1.w;
        Bs[lcol + 0][lrow] = b0.x; Bs[lcol + 1][lrow] = b0.y;
        Bs[lcol + 2][lrow] = b0.z; Bs[lcol + 3][lrow] = b0.w;
        Bs[lcol + 0][lrow + 64] = b1.x; Bs[lcol + 1][lrow + 64] = b1.y;
        Bs[lcol + 2][lrow + 64] = b1.z; Bs[lcol + 3][lrow + 64] = b1.w;
        __syncthreads();

        if (k0 + 16 < Dd) {
            a0 = *(const float4*)(Aptr + k0 + 16);
            a1 = *(const float4*)(Aptr + (size_t)64 * Dd + k0 + 16);
            b0 = *(const float4*)(Wptr + k0 + 16);
            b1 = *(const float4*)(Wptr + (size_t)64 * Dd + k0 + 16);
        }

#pragma unroll
        for (int k = 0; k < 16; k++) {
            float ar[8];
            *(float4*)(ar) = *(const float4*)&As[k][ty * 8];
            *(float4*)(ar + 4) = *(const float4*)&As[k][ty * 8 + 4];
            unsigned long long brp[4];
            const unsigned long long* b64 = (const unsigned long long*)&Bs[k][tx * 8];
            brp[0] = b64[0]; brp[1] = b64[1]; brp[2] = b64[2]; brp[3] = b64[3];
#pragma unroll
            for (int i = 0; i < 8; i++) {
                unsigned long long ad = pk2(ar[i], ar[i]);
#pragma unroll
                for (int j = 0; j < 4; j++) fma2(acc2[i][j], ad, brp[j]);
            }
        }
    }

    float bj[8];
#pragma unroll
    for (int j = 0; j < 8; j++) bj[j] = bias[n0 + tx * 8 + j];
#pragma unroll
    for (int i = 0; i < 8; i++) {
        float* Crow = g_pre + (size_t)(m0 + ty * 8 + i) * Dd + n0 + tx * 8;
        float c[8];
#pragma unroll
        for (int j = 0; j < 4; j++) {
            float2 f = up2(acc2[i][j]);
            c[2 * j] = f.x + bj[2 * j];
            c[2 * j + 1] = f.y + bj[2 * j + 1];
        }
        *(float4*)(Crow) = make_float4(c[0], c[1], c[2], c[3]);
        *(float4*)(Crow + 4) = make_float4(c[4], c[5], c[6], c[7]);
    }
}

// fast tanh: (e^{2x}-1)/(e^{2x}+1), __expf-based (rel err ~1e-6)
__device__ __forceinline__ float ftanh(float x) {
    float e = __expf(2.f * x);
    return 1.f - 2.f / (e + 1.f);
}

// ---------------- persistent recurrence, 4 independent batch groups --------
// 128 CTAs = 4 groups x 32 CTAs. Group g owns batches [4g, 4g+4) (independent
// chains -> independent barriers). CTA owns 32 dims x its group's 4 batches.
// W slice (128KB) persistent in dynamic SMEM. h streamed from L2 via LDG.cg.
// Warp = 8 dims x 4 batches x k-half (4 dim-groups x 2 k-halves = 8 warps).
// Barrier: acq_rel atomic arrivals; last arriver st.release's a write-once
// release word; one poller per CTA spins with ld.acquire on the clean line.
__global__ void __launch_bounds__(256, 1) recurrent_kernel(
        const float* __restrict__ z, const float* __restrict__ h0,
        float* __restrict__ outs, float* __restrict__ hall) {
    extern __shared__ float smem[];
    float* sW = smem;                 // [DC][Dd] = 128 KB
    float* red = smem + DC * Dd;      // [128]

    const int tid = threadIdx.x, bid = blockIdx.x;
    const int grp = bid >> 5;               // sync group / batch group
    const int dbase = (bid & 31) * DC;      // this CTA's dim range
    const int bbase = grp * BC;             // this CTA's batch range
    unsigned* arr_p = &g_arr[grp * 32];
    unsigned* rel_p = &g_rel[grp * 32];

    // preload my W_h_eff rows (persist across all steps)
    {
        const float4* wsrc = (const float4*)(g_WhEff + (size_t)dbase * Dd);
        for (int i = tid; i < DC * Dd / 4; i += 256) ((float4*)sW)[i] = wsrc[i];
    }
    // write h_all[0] stripe (pure output; consumers read h0 input directly)
    if (tid < 128) {
        int b = bbase + (tid & 3);
        int d = dbase + (tid >> 5) * 8 + ((tid >> 2) & 7);
        hall[b * Dd + d] = h0[b * Dd + d];
    }
    __syncthreads();

    const int warp = tid >> 5, lane = tid & 31;
    const int dg = warp >> 1;   // dim group (8 dims each)
    const int kw = warp & 1;    // k-split half
    const ulonglong2* w128 = (const ulonglong2*)sW;
    const int kbase = kw * 128 + lane;  // float4-granule index base

    // epilogue mapping (tid < 128): one (batch, dim) output per thread,
    // matching red[] layout: red[dg*32 + lane], lane -> (d_local=lane>>2, b=lane&3)
    const int eb = bbase + (tid & 3);
    const int ed = dbase + (tid >> 5) * 8 + ((tid >> 2) & 7);

    for (int t = 0; t < Tt; t++) {
        const size_t off_e = (size_t)t * Bb * Dd + (size_t)eb * Dd + ed;
        float pre_v = 0.f, z_v = 0.f;
        if (tid < 128) {       // DRAM prefetch; overlaps the barrier wait
            pre_v = __ldcg(g_pre + off_e);
            z_v = __ldcg(z + off_e);
        }

        // group barrier wait (skip at t=0: h0 is a kernel input)
        if (t > 0) {
            if (tid == 0) {
                unsigned v;
                do {
                    asm volatile("ld.acquire.gpu.global.u32 %0, [%1];"
                                 : "=r"(v) : "l"(rel_p) : "memory");
                } while (v < (unsigned)t);
            }
            __syncthreads();
        }

        // stream h straight from L2 (my group's 4 batches only)
        const ulonglong2* hsrc = (const ulonglong2*)
            ((t == 0) ? h0 : (hall + (size_t)t * Bb * Dd));

        unsigned long long acc[32];
#pragma unroll
        for (int i = 0; i < 32; i++) acc[i] = 0ULL;
#pragma unroll
        for (int it = 0; it < 4; it++) {
            ulonglong2 hv[4];
#pragma unroll
            for (int b = 0; b < 4; b++)
                hv[b] = __ldcg(hsrc + (size_t)(bbase + b) * (Dd / 4) + kbase + it * 32);
            ulonglong2 wv[8];
#pragma unroll
            for (int d = 0; d < 8; d++)
                wv[d] = w128[(dg * 8 + d) * 256 + kbase + it * 32];
#pragma unroll
            for (int d = 0; d < 8; d++)
#pragma unroll
                for (int b = 0; b < 4; b++) {
                    fma2(acc[d * 4 + b], wv[d].x, hv[b].x);
                    fma2(acc[d * 4 + b], wv[d].y, hv[b].y);
                }
        }

        // butterfly-fold: lane l ends owning output l (d_local = l>>2, b = l&3)
#pragma unroll
        for (int off = 16; off > 0; off >>= 1) {
#pragma unroll
            for (int j = 0; j < off; j++) {
                unsigned long long send = (lane & off) ? acc[j] : acc[j + off];
                unsigned long long recv = __shfl_xor_sync(0xffffffffu, send, off);
                acc[j] = add2((lane & off) ? acc[j + off] : acc[j], recv);
            }
        }
        float2 f2 = up2(acc[0]);
        const float myv = f2.x + f2.y;

        // cross-k-half combine through smem
        const int ridx = dg * 32 + lane;
        if (kw == 0) red[ridx] = myv;
        __syncthreads();
        if (kw == 1) red[ridx] += myv;
        __syncthreads();

        // epilogue: 128 threads, one output each
        float hn = 0.f;
        if (tid < 128) {
            hn = ftanh(red[tid] + pre_v);
            hall[off_e + Bb * Dd] = hn;   // h_all[t+1]
        }
        __syncthreads();                  // all stores issued before arrival
        if (tid == 0) {
            unsigned old;
            asm volatile("atom.acq_rel.gpu.global.add.u32 %0, [%1], %2;"
                         : "=r"(old) : "l"(arr_p), "r"(1u) : "memory");
            if (old == (unsigned)((t + 1) * CPG - 1)) {
                asm volatile("st.release.gpu.global.u32 [%0], %1;"
                             :: "l"(rel_p), "r"((unsigned)(t + 1)) : "memory");
            }
        }
        // silu gate off the critical path
        if (tid < 128) {
            float sg = z_v / (1.f + __expf(-z_v));
            outs[off_e] = hn * sg;
        }
    }
}

// ---------------- launch ----------------
extern "C" void kernel_launch(void* const* d_in, const int* in_sizes, int n_in,
                              void* d_out, int out_size) {
    const float* x   = (const float*)d_in[0];  // [T,B,D]
    const float* z   = (const float*)d_in[1];  // [T,B,D]
    const float* h0  = (const float*)d_in[2];  // [B,D]
    const float* Wx  = (const float*)d_in[3];  // [D,D]
    const float* Wh  = (const float*)d_in[4];  // [D,D]
    const float* lr  = (const float*)d_in[5];  // [D]
    const float* bia = (const float*)d_in[6];  // [D]
    const float* u0  = (const float*)d_in[7];  // [D]

    float* outs = (float*)d_out;                         // [T,B,D]
    float* hall = (float*)d_out + (size_t)Tt * Bb * Dd;  // [T+1,B,D]

    const size_t rec_smem = (size_t)(DC * Dd + 128) * sizeof(float);  // ~128.5 KB
    cudaFuncSetAttribute(recurrent_kernel,
                         cudaFuncAttributeMaxDynamicSharedMemorySize,
                         (int)rec_smem);

    init_kernel<<<1, 128>>>();
    power_iter_kernel<<<1, 1024>>>(Wh, u0);
    scale_wh_kernel<<<Dd, 256>>>(Wh, lr);
    {
        dim3 grid(Dd / 128, (Tt * Bb) / 128);  // (8, 128)
        gemm_kernel<<<grid, 256>>>(x, Wx, bia);
    }
    dummy_kernel<<<1, 1>>>();   // aligns recurrent_kernel with ncu -s 5 -c 1
    recurrent_kernel<<<NBLK, 256, rec_smem>>>(z, h0, outs, hall);
}